// round 9
// baseline (speedup 1.0000x reference)
#include <cuda_runtime.h>
#include <cstdint>

// out[b, 0:128]   = emb[idx[b], :]    (128 f32)
// out[b, 128:146] = genre[idx[b], :]  (18 f32)
// idx is int32 (JAX downcasts int64 without x64).
//
// Warp handles 4 consecutive rows (one int4 idx broadcast -> 4 independent
// emb gathers + 4 predicated genre gathers in flight).
// Output stores use st.global.wt (__stwt): WRITE-THROUGH, so the 612 MB
// output stream does not allocate/occupy L2 lines at all -> the 58 MB
// tables stay L2-resident -> gather DRAM re-reads (~120 MB) collapse.
// (R4/R7 showed evict-priority hints only partially work; .wt removes the
// stream from L2 capacity entirely.)

#define ROWS_PER_WARP 4

__global__ void __launch_bounds__(256)
item_gather_concat_kernel(const int*    __restrict__ idx,
                          const float4* __restrict__ emb,   // [N, 32] float4
                          const float2* __restrict__ gen,   // [N, 9]  float2
                          float2*       __restrict__ out,   // [B, 73] float2
                          int B)
{
    const int lane  = threadIdx.x & 31;
    const int gwarp = (int)((blockIdx.x * (unsigned)blockDim.x + threadIdx.x) >> 5);
    const int r0    = gwarp * ROWS_PER_WARP;

    if (r0 + ROWS_PER_WARP <= B) {
        int4 iv = __ldcs((const int4*)(idx + r0));   // read-once broadcast
        int items[4] = {iv.x, iv.y, iv.z, iv.w};

        // Issue all independent gathers first (MLP), then store.
        float4 e[4];
        float2 g[4];
        #pragma unroll
        for (int j = 0; j < 4; j++)
            e[j] = __ldg(&emb[(size_t)items[j] * 32 + lane]);
        #pragma unroll
        for (int j = 0; j < 4; j++)
            if (lane < 9)
                g[j] = __ldg(&gen[(size_t)items[j] * 9 + lane]);

        #pragma unroll
        for (int j = 0; j < 4; j++) {
            float2* o = out + (size_t)(r0 + j) * 73;   // 8B-aligned rows
            __stwt(&o[lane * 2 + 0], make_float2(e[j].x, e[j].y));
            __stwt(&o[lane * 2 + 1], make_float2(e[j].z, e[j].w));
            if (lane < 9)
                __stwt(&o[64 + lane], g[j]);
        }
    } else {
        // Tail fallback (unused for B = 1M): one row at a time.
        for (int r = r0; r < B && r < r0 + ROWS_PER_WARP; r++) {
            int item = idx[r];
            float4 e = __ldg(&emb[(size_t)item * 32 + lane]);
            float2* o = out + (size_t)r * 73;
            o[lane * 2 + 0] = make_float2(e.x, e.y);
            o[lane * 2 + 1] = make_float2(e.z, e.w);
            if (lane < 9)
                o[64 + lane] = __ldg(&gen[(size_t)item * 9 + lane]);
        }
    }
}

extern "C" void kernel_launch(void* const* d_in, const int* in_sizes, int n_in,
                              void* d_out, int out_size)
{
    const int*    idx = (const int*)   d_in[0];
    const float4* emb = (const float4*)d_in[1];
    const float2* gen = (const float2*)d_in[2];
    float2*       out = (float2*)d_out;

    int B = in_sizes[0];                                   // 1048576
    int rowsPerBlock = 8 * ROWS_PER_WARP;                  // 8 warps/block
    int blocks = (B + rowsPerBlock - 1) / rowsPerBlock;    // 32768

    item_gather_concat_kernel<<<blocks, 256>>>(idx, emb, gen, out, B);
}